// round 17
// baseline (speedup 1.0000x reference)
#include <cuda_runtime.h>
#include <cuda_bf16.h>
#include <math.h>

// Problem constants (fixed shapes)
#define BB 4
#define HH 1024
#define WW 1920
#define HW (HH * WW)                 // 1,966,080
#define NPIX (BB * HW)               // 7,864,320
#define ALPHA 100.0f
#define EPSN 1e-7f

// Scratch: splat accumulator [B][H][W][4] (RGB*em, em), 16B/pixel (~126 MB)
__device__ __align__(16) float g_acc[(size_t)NPIX * 4];
// Scratch: rgb2 packed as RGBX float4 per pixel (~126 MB) for vector gathers
__device__ __align__(16) float4 g_rgbx[(size_t)NPIX];

// ---------------------------------------------------------------------------
// Zero accumulator (writer-only streaming kernel)
// ---------------------------------------------------------------------------
__global__ void __launch_bounds__(256)
zero_acc_kernel()
{
    int i = blockIdx.x * blockDim.x + threadIdx.x;
    ((float4*)g_acc)[i] = make_float4(0.f, 0.f, 0.f, 0.f);
}

// ---------------------------------------------------------------------------
// Pack rgb2 planar -> RGBX float4 (coalesced read + write)
// grid = (15, HH, BB), block = 128
// ---------------------------------------------------------------------------
__global__ void __launch_bounds__(128)
pack_rgbx_kernel(const float* __restrict__ rgb2)
{
    int x = blockIdx.x * 128 + threadIdx.x;
    int y = blockIdx.y;
    int b = blockIdx.z;
    int rem = y * WW + x;

    const float* r2 = rgb2 + (size_t)b * 3 * HW;
    g_rgbx[(size_t)b * HW + rem] =
        make_float4(r2[rem], r2[HW + rem], r2[2 * HW + rem], 0.f);
}

// ---------------------------------------------------------------------------
// Splat kernel: 1 thread = 1 pixel; 3D grid (no integer divisions).
// Bilinear gather from packed RGBX (4 x LDG.128), bilinear scatter (4 x RED.128).
// ---------------------------------------------------------------------------
__global__ void __launch_bounds__(128)
splat_metric_kernel(const float* __restrict__ rgb1,
                    const float* __restrict__ flow_t,
                    const float* __restrict__ flow12,
                    float* __restrict__ out_metric)
{
    int x = blockIdx.x * 128 + threadIdx.x;
    int y = blockIdx.y;
    int b = blockIdx.z;
    int rem = y * WW + x;

    // ---- Backwarp gather from packed rgb2 (bilinear, zeros padding) ----
    const float* f12 = flow12 + (size_t)b * 2 * HW;
    float px = (float)x + f12[rem];
    float py = (float)y + f12[HW + rem];
    float x0f = floorf(px), y0f = floorf(py);
    int   x0  = (int)x0f,   y0  = (int)y0f;
    float wx  = px - x0f,   wy  = py - y0f;

    const float4* rx = g_rgbx + (size_t)b * HW;
    float bw0 = 0.f, bw1 = 0.f, bw2 = 0.f;
    {
        float wtx[2] = {1.f - wx, wx};
        float wty[2] = {1.f - wy, wy};
        #pragma unroll
        for (int ty = 0; ty < 2; ty++) {
            int yi = y0 + ty;
            int yc = min(max(yi, 0), HH - 1);
            bool vy = (yi >= 0) & (yi < HH);
            #pragma unroll
            for (int tx = 0; tx < 2; tx++) {
                int xi = x0 + tx;
                int xc = min(max(xi, 0), WW - 1);
                bool v = vy & (xi >= 0) & (xi < WW);
                float w = wtx[tx] * wty[ty] * (v ? 1.f : 0.f);
                float4 g = __ldg(rx + (yc * WW + xc));
                bw0 += w * g.x;
                bw1 += w * g.y;
                bw2 += w * g.z;
            }
        }
    }

    // ---- Metric (channel-mean L1) + splat weight ----
    const float* r1 = rgb1 + (size_t)b * 3 * HW;
    float c0 = r1[rem];
    float c1 = r1[HW + rem];
    float c2 = r1[2 * HW + rem];
    float metric = (fabsf(c0 - bw0) + fabsf(c1 - bw1) + fabsf(c2 - bw2)) * (1.0f / 3.0f);
    out_metric[(size_t)b * HW + rem] = metric;

    float m  = fminf(fmaxf(-ALPHA * metric, -ALPHA), ALPHA);
    float em = __expf(m);

    // ---- Forward splat (bilinear scatter-add) with flow_t ----
    const float* ft = flow_t + (size_t)b * 2 * HW;
    float qx = (float)x + ft[rem];
    float qy = (float)y + ft[HW + rem];
    float qx0f = floorf(qx), qy0f = floorf(qy);
    int   qx0  = (int)qx0f,  qy0  = (int)qy0f;
    float ux   = qx - qx0f,  uy   = qy - qy0f;

    float v0 = c0 * em, v1 = c1 * em, v2 = c2 * em;
    float* acc = g_acc + (size_t)b * HW * 4;

    float utx[2] = {1.f - ux, ux};
    float uty[2] = {1.f - uy, uy};
    #pragma unroll
    for (int ty = 0; ty < 2; ty++) {
        int yi = qy0 + ty;
        if (yi < 0 || yi >= HH) continue;
        #pragma unroll
        for (int tx = 0; tx < 2; tx++) {
            int xi = qx0 + tx;
            if (xi < 0 || xi >= WW) continue;
            float w = utx[tx] * uty[ty];
            float4* p = (float4*)(acc + (size_t)(yi * WW + xi) * 4);
            atomicAdd(p, make_float4(v0 * w, v1 * w, v2 * w, em * w));
        }
    }
}

// ---------------------------------------------------------------------------
// Normalize kernel: 1 thread = 1 pixel, read-only on g_acc (coalesced float4).
// ---------------------------------------------------------------------------
__global__ void __launch_bounds__(128)
normalize_kernel(float* __restrict__ out_img)
{
    int x = blockIdx.x * 128 + threadIdx.x;
    int y = blockIdx.y;
    int b = blockIdx.z;
    int rem = y * WW + x;

    float4 v = *(const float4*)(g_acc + ((size_t)b * HW + rem) * 4);
    float inv = 1.0f / (v.w + EPSN);

    float* o = out_img + (size_t)b * 3 * HW;
    o[rem]          = v.x * inv;
    o[HW + rem]     = v.y * inv;
    o[2 * HW + rem] = v.z * inv;
}

extern "C" void kernel_launch(void* const* d_in, const int* in_sizes, int n_in,
                              void* d_out, int out_size)
{
    const float* rgb1   = (const float*)d_in[0];
    const float* rgb2   = (const float*)d_in[1];
    const float* flow_t = (const float*)d_in[2];  // flow_src1_to_tgt
    const float* flow12 = (const float*)d_in[3];  // flow_src1_to_src2

    float* out_img    = (float*)d_out;                        // [B,3,H,W]
    float* out_metric = (float*)d_out + (size_t)BB * 3 * HW;  // [B,1,H,W]

    // zero_acc: NPIX float4 cells, 256 threads each -> 30720 blocks
    zero_acc_kernel<<<NPIX / 256, 256, 0, 0>>>();

    dim3 grid(WW / 128, HH, BB);   // (15, 1024, 4), block = 128
    pack_rgbx_kernel<<<grid, 128, 0, 0>>>(rgb2);
    splat_metric_kernel<<<grid, 128, 0, 0>>>(rgb1, flow_t, flow12, out_metric);
    normalize_kernel<<<grid, 128, 0, 0>>>(out_img);
}